// round 9
// baseline (speedup 1.0000x reference)
#include <cuda_runtime.h>

#define NF      26
#define EMB     128
#define ROW_IN  (NF * EMB)               // 3328
#define NPAIR   325                      // 26*25/2
#define DENSE   128
#define ROW_OUT (ROW_IN + NPAIR + DENSE) // 3781
#define RPB     4                        // rows per block (2 warps per row, 256 thr)
#define NB      11                       // ceil(325/32) flush batches

__global__ __launch_bounds__(256, 2)
void fi_kernel(const float* __restrict__ sparse,
               const float* __restrict__ dense,
               float* __restrict__ out,
               int batch)
{
    __shared__ float s_red[RPB][NB * 32];

    const int warp = threadIdx.x >> 5;
    const int lane = threadIdx.x & 31;
    const int rloc = warp >> 1;            // row within block
    const int half = warp & 1;             // which 64-element half of EMB
    const int r    = blockIdx.x * RPB + rloc;
    const bool active = r < batch;

    // lane l of half h holds elements {h*64+l, h*64+32+l} of every feature
    float a0[NF], a1[NF];
    float red[NB];

    float* __restrict__ orow = out + (size_t)r * ROW_OUT;

    if (active) {
        const float* __restrict__ in = sparse + (size_t)r * ROW_IN + half * 64 + lane;

        // ---- load row (coalesced LDG.32, full 128B lines per warp) ----
        #pragma unroll
        for (int f = 0; f < NF; f++) {
            a0[f] = in[f * EMB];
            a1[f] = in[f * EMB + 32];
        }

        // ---- sparse passthrough, coalesced straight from registers ----
        #pragma unroll
        for (int f = 0; f < NF; f++) {
            orow[f * EMB + half * 64 + lane]      = a0[f];
            orow[f * EMB + half * 64 + 32 + lane] = a1[f];
        }

        // ---- dense passthrough ----
        {
            const float* __restrict__ dr = dense + (size_t)r * DENSE + half * 64 + lane;
            orow[ROW_IN + NPAIR + half * 64 + lane]      = dr[0];
            orow[ROW_IN + NPAIR + half * 64 + 32 + lane] = dr[32];
        }

        // ---- gram upper triangle: per-lane partials over this warp's 64 elems ----
        float vals[32];
        int cnt = 0;      // constant-folded under full unroll
        int b   = 0;

        #pragma unroll
        for (int f = 0; f < NF - 1; f++) {
            #pragma unroll
            for (int g = f + 1; g < NF; g++) {
                vals[cnt] = a0[f] * a0[g] + a1[f] * a1[g];
                cnt++;
                if (cnt == 32) {
                    // multi-value butterfly: 31 shuffles -> lane j holds output j
                    #pragma unroll
                    for (int m = 16; m >= 1; m >>= 1) {
                        #pragma unroll
                        for (int i = 0; i < m; i++) {
                            const bool hi = (lane & m) != 0;
                            float send = hi ? vals[i]     : vals[i + m];
                            float keep = hi ? vals[i + m] : vals[i];
                            float recv = __shfl_xor_sync(0xFFFFFFFFu, send, m);
                            vals[i] = keep + recv;
                        }
                    }
                    red[b] = vals[0];
                    b++;
                    cnt = 0;
                }
            }
        }
        // tail: 325 % 32 = 5 valid; garbage in slots 5..31 only affects
        // lanes 5..31 of the last batch, which are never stored.
        {
            #pragma unroll
            for (int m = 16; m >= 1; m >>= 1) {
                #pragma unroll
                for (int i = 0; i < m; i++) {
                    const bool hi = (lane & m) != 0;
                    float send = hi ? vals[i]     : vals[i + m];
                    float keep = hi ? vals[i + m] : vals[i];
                    float recv = __shfl_xor_sync(0xFFFFFFFFu, send, m);
                    vals[i] = keep + recv;
                }
            }
            red[NB - 1] = vals[0];
        }
    }

    // ---- cross-warp combine: half 0 stages, half 1 adds + stores ----
    if (active && half == 0) {
        #pragma unroll
        for (int b = 0; b < NB; b++)
            s_red[rloc][b * 32 + lane] = red[b];
    }
    __syncthreads();
    if (active && half == 1) {
        #pragma unroll
        for (int b = 0; b < NB; b++) {
            const int idx = b * 32 + lane;
            float v = red[b] + s_red[rloc][b * 32 + lane];
            if (idx < NPAIR) orow[ROW_IN + idx] = v;
        }
    }
}

extern "C" void kernel_launch(void* const* d_in, const int* in_sizes, int n_in,
                              void* d_out, int out_size)
{
    const float* sparse = (const float*)d_in[0];
    const float* dense  = (const float*)d_in[1];
    float* out = (float*)d_out;

    const int batch = in_sizes[0] / ROW_IN;          // 16384
    const int grid  = (batch + RPB - 1) / RPB;       // 4096
    fi_kernel<<<grid, RPB * 2 * 32>>>(sparse, dense, out, batch);
}

// round 12
// speedup vs baseline: 8.1055x; 8.1055x over previous
#include <cuda_runtime.h>

#define NF      26
#define EMB     128
#define ROW_IN  (NF * EMB)               // 3328
#define NPAIR   325                      // 26*25/2
#define DENSE   128
#define ROW_OUT (ROW_IN + NPAIR + DENSE) // 3781
#define NB      11                       // ceil(325/32)
#define RPB     2                        // rows per block (2 warps each -> 128 thr)

// compile-time pair decode: p in [0,325) -> (f,g), f<g, row-major upper triangle
__host__ __device__ constexpr int pf_(int p) {
    int f = 0, c = NF - 1;
    while (p >= c) { p -= c; f++; c--; }
    return f;
}
__host__ __device__ constexpr int pg_(int p) {
    int f = 0, c = NF - 1;
    while (p >= c) { p -= c; f++; c--; }
    return f + 1 + p;
}

// ---- static product fill for batch B, slot I ----
template<int B, int I>
__device__ __forceinline__ void batch_prods(const float (&a0)[NF], const float (&a1)[NF],
                                            float (&vals)[32])
{
    constexpr int p = B * 32 + I;
    if constexpr (p < NPAIR) {
        constexpr int f = pf_(p);
        constexpr int g = pg_(p);
        vals[I] = a0[f] * a0[g] + a1[f] * a1[g];
    } else {
        vals[I] = 0.f;
    }
    if constexpr (I + 1 < 32) batch_prods<B, I + 1>(a0, a1, vals);
}

// ---- batch B: products + 31-shuffle multi-value butterfly -> red[B] (lane j = output j) ----
template<int B>
__device__ __forceinline__ void gram_batches(const float (&a0)[NF], const float (&a1)[NF],
                                             float (&red)[NB], int lane)
{
    float vals[32];
    batch_prods<B, 0>(a0, a1, vals);

    #pragma unroll
    for (int m = 16; m >= 1; m >>= 1) {
        const bool hi = (lane & m) != 0;
        #pragma unroll
        for (int i = 0; i < m; i++) {
            float send = hi ? vals[i]     : vals[i + m];
            float keep = hi ? vals[i + m] : vals[i];
            vals[i] = keep + __shfl_xor_sync(0xFFFFFFFFu, send, m);
        }
    }
    red[B] = vals[0];

    if constexpr (B + 1 < NB) gram_batches<B + 1>(a0, a1, red, lane);
}

__global__ __launch_bounds__(128)
void fi_kernel(const float* __restrict__ sparse,
               const float* __restrict__ dense,
               float* __restrict__ out,
               int batch)
{
    __shared__ float s_red[RPB][NB * 32];

    const int warp = threadIdx.x >> 5;
    const int lane = threadIdx.x & 31;
    const int rloc = warp >> 1;            // row within block
    const int half = warp & 1;             // which 64-element half of EMB
    const int r    = blockIdx.x * RPB + rloc;
    const bool active = r < batch;

    float a0[NF], a1[NF];
    float red[NB];
    float* __restrict__ orow = out + (size_t)r * ROW_OUT;

    if (active) {
        // lane l of half h holds elements {h*64+l, h*64+32+l} of every feature
        const float* __restrict__ in = sparse + (size_t)r * ROW_IN + half * 64 + lane;

        #pragma unroll
        for (int f = 0; f < NF; f++) {
            a0[f] = in[f * EMB];
            a1[f] = in[f * EMB + 32];
        }

        // sparse passthrough, coalesced from registers
        #pragma unroll
        for (int f = 0; f < NF; f++) {
            orow[f * EMB + half * 64 + lane]      = a0[f];
            orow[f * EMB + half * 64 + 32 + lane] = a1[f];
        }

        // dense passthrough
        {
            const float* __restrict__ dr = dense + (size_t)r * DENSE + half * 64 + lane;
            orow[ROW_IN + NPAIR + half * 64 + lane]      = dr[0];
            orow[ROW_IN + NPAIR + half * 64 + 32 + lane] = dr[32];
        }

        // gram upper triangle: 11 fully static batches
        gram_batches<0>(a0, a1, red, lane);
    }

    // cross-warp combine: half 0 stages, half 1 adds + stores
    if (active && half == 0) {
        #pragma unroll
        for (int b = 0; b < NB; b++)
            s_red[rloc][b * 32 + lane] = red[b];
    }
    __syncthreads();
    if (active && half == 1) {
        #pragma unroll
        for (int b = 0; b < NB; b++) {
            const int idx = b * 32 + lane;
            if (idx < NPAIR)
                orow[ROW_IN + idx] = red[b] + s_red[rloc][b * 32 + lane];
        }
    }
}

extern "C" void kernel_launch(void* const* d_in, const int* in_sizes, int n_in,
                              void* d_out, int out_size)
{
    const float* sparse = (const float*)d_in[0];
    const float* dense  = (const float*)d_in[1];
    float* out = (float*)d_out;

    const int batch = in_sizes[0] / ROW_IN;          // 16384
    const int grid  = (batch + RPB - 1) / RPB;       // 8192
    fi_kernel<<<grid, RPB * 2 * 32>>>(sparse, dense, out, batch);
}